// round 1
// baseline (speedup 1.0000x reference)
#include <cuda_runtime.h>
#include <cuda_bf16.h>
#include <cstdint>

// Problem constants (fixed by the reference)
#define NSIDE 64
#define NPIX  (12 * NSIDE * NSIDE)   // 49152
#define B     8
#define C     16
#define NN    524288                 // N

#define BINS  (B * NPIX)             // 393216

// Scratch: per-(batch,pixel) running sum and count. Device globals (no allocs).
__device__ float g_sum[BINS];
__device__ float g_cnt[BINS];

// ---------------------------------------------------------------------------
// Pass 1: zero the scratch. 2*393216 floats, float4-vectorized.
// ---------------------------------------------------------------------------
__global__ void zero_kernel() {
    int i = blockIdx.x * blockDim.x + threadIdx.x;   // 0 .. BINS/4-1
    float4 z = make_float4(0.f, 0.f, 0.f, 0.f);
    reinterpret_cast<float4*>(g_sum)[i] = z;
    reinterpret_cast<float4*>(g_cnt)[i] = z;
}

// ---------------------------------------------------------------------------
// Pass 2: scatter-accumulate. Each thread handles 4 consecutive elements of
// one batch's channel-0 slice (N divisible by 4, threads never straddle a
// batch boundary since N/4 divides evenly).
// vals layout [B, C, N] -> channel 0 of batch b starts at b*C*N.
// ---------------------------------------------------------------------------
__global__ void accum_kernel(const float* __restrict__ vals,
                             const int*   __restrict__ pix) {
    const long long t = (long long)blockIdx.x * blockDim.x + threadIdx.x;
    // t in [0, B*N/4)
    const int per_batch = NN / 4;                 // 131072 vec4 per batch
    const int b = (int)(t / per_batch);
    const int v = (int)(t % per_batch);

    const float4 vv = reinterpret_cast<const float4*>(
        vals + (long long)b * C * NN)[v];
    const int4 pp = reinterpret_cast<const int4*>(
        pix + (long long)b * NN)[v];

    float* __restrict__ sum = g_sum + b * NPIX;
    float* __restrict__ cnt = g_cnt + b * NPIX;

    atomicAdd(sum + pp.x, vv.x); atomicAdd(cnt + pp.x, 1.0f);
    atomicAdd(sum + pp.y, vv.y); atomicAdd(cnt + pp.y, 1.0f);
    atomicAdd(sum + pp.z, vv.z); atomicAdd(cnt + pp.z, 1.0f);
    atomicAdd(sum + pp.w, vv.w); atomicAdd(cnt + pp.w, 1.0f);
}

// ---------------------------------------------------------------------------
// Pass 3: compute mean and broadcast across C=16 output channels.
// One thread per (b, pixel): reads sum/cnt, writes 16 floats = 4x float4.
// Output layout [B, NPIX, C], C contiguous.
// ---------------------------------------------------------------------------
__global__ void write_kernel(float* __restrict__ out) {
    int i = blockIdx.x * blockDim.x + threadIdx.x;   // 0 .. BINS-1
    float s = g_sum[i];
    float c = fmaxf(g_cnt[i], 1.0f);
    float m = s / c;
    float4 mv = make_float4(m, m, m, m);
    float4* __restrict__ o = reinterpret_cast<float4*>(out) + (long long)i * 4;
    o[0] = mv; o[1] = mv; o[2] = mv; o[3] = mv;
}

// ---------------------------------------------------------------------------
extern "C" void kernel_launch(void* const* d_in, const int* in_sizes, int n_in,
                              void* d_out, int out_size) {
    const float* vals = (const float*)d_in[0];   // [B, C, N] f32
    const int*   pix  = (const int*)d_in[1];     // [B, N] i32
    float*       out  = (float*)d_out;           // [B, NPIX, C] f32

    (void)in_sizes; (void)n_in; (void)out_size;

    {
        const int n = BINS / 4;                  // 98304
        zero_kernel<<<n / 256, 256>>>();
    }
    {
        const long long n = (long long)B * NN / 4;   // 1,048,576
        accum_kernel<<<(unsigned)(n / 256), 256>>>(vals, pix);
    }
    {
        write_kernel<<<BINS / 256, 256>>>(out);
    }
}

// round 2
// speedup vs baseline: 1.4911x; 1.4911x over previous
#include <cuda_runtime.h>
#include <cuda_bf16.h>
#include <cstdint>

// Problem constants (fixed by the reference)
#define NSIDE 64
#define NPIX  (12 * NSIDE * NSIDE)   // 49152
#define B     8
#define C     16
#define NN    524288                 // N

#define BINS  (B * NPIX)             // 393216

// Scratch: per-(batch,pixel) {sum, count} pair, interleaved so one v2 REDG
// updates both. Zero-initialized at module load; write_kernel restores zeros
// after reading, so every kernel_launch sees a clean scratch (graph-replay
// safe, no zeroing kernel needed).
__device__ float2 g_bin[BINS];

// ---------------------------------------------------------------------------
// Pass 1: scatter-accumulate. Each thread handles 4 consecutive elements of
// one batch's channel-0 slice via float4/int4 loads. One red.global.add.v2.f32
// per element updates {sum, cnt} in a single L2 atomic transaction.
// vals layout [B, C, N] -> channel 0 of batch b starts at b*C*N.
// ---------------------------------------------------------------------------
__device__ __forceinline__ void red_v2(float2* p, float v) {
    asm volatile("red.global.add.v2.f32 [%0], {%1, %2};"
                 :: "l"(p), "f"(v), "f"(1.0f) : "memory");
}

__global__ void accum_kernel(const float* __restrict__ vals,
                             const int*   __restrict__ pix) {
    const int t = blockIdx.x * blockDim.x + threadIdx.x;  // 0 .. B*N/4-1
    const int per_batch = NN / 4;                 // 131072 vec4 per batch
    const int b = t / per_batch;
    const int v = t % per_batch;

    const float4 vv = reinterpret_cast<const float4*>(
        vals + (long long)b * C * NN)[v];
    const int4 pp = reinterpret_cast<const int4*>(
        pix + (long long)b * NN)[v];

    float2* __restrict__ bin = g_bin + b * NPIX;

    red_v2(bin + pp.x, vv.x);
    red_v2(bin + pp.y, vv.y);
    red_v2(bin + pp.z, vv.z);
    red_v2(bin + pp.w, vv.w);
}

// ---------------------------------------------------------------------------
// Pass 2: compute mean, broadcast across C=16 output channels, and reset the
// bin to zero for the next graph replay.
// One thread per (b, pixel): reads {sum,cnt}, writes 16 floats = 4x float4.
// Output layout [B, NPIX, C], C contiguous.
// ---------------------------------------------------------------------------
__global__ void write_kernel(float* __restrict__ out) {
    int i = blockIdx.x * blockDim.x + threadIdx.x;   // 0 .. BINS-1
    float2 sc = g_bin[i];
    g_bin[i] = make_float2(0.f, 0.f);                // self-clean for replay
    float m = sc.x / fmaxf(sc.y, 1.0f);
    float4 mv = make_float4(m, m, m, m);
    float4* __restrict__ o = reinterpret_cast<float4*>(out) + (long long)i * 4;
    o[0] = mv; o[1] = mv; o[2] = mv; o[3] = mv;
}

// ---------------------------------------------------------------------------
extern "C" void kernel_launch(void* const* d_in, const int* in_sizes, int n_in,
                              void* d_out, int out_size) {
    const float* vals = (const float*)d_in[0];   // [B, C, N] f32
    const int*   pix  = (const int*)d_in[1];     // [B, N] i32
    float*       out  = (float*)d_out;           // [B, NPIX, C] f32

    (void)in_sizes; (void)n_in; (void)out_size;

    {
        const int n = B * (NN / 4);              // 1,048,576 threads
        accum_kernel<<<n / 256, 256>>>(vals, pix);
    }
    {
        write_kernel<<<BINS / 256, 256>>>(out);
    }
}

// round 4
// speedup vs baseline: 1.5884x; 1.0653x over previous
#include <cuda_runtime.h>
#include <cuda_bf16.h>
#include <cstdint>

// Problem constants (fixed by the reference)
#define NSIDE 64
#define NPIX  (12 * NSIDE * NSIDE)   // 49152
#define B     8
#define C     16
#define NN    524288                 // N

#define BINS  (B * NPIX)             // 393216

// Scratch: per-(batch,pixel) {sum, count} pair, interleaved so one v2 REDG
// updates both. Zero-initialized at module load; write_kernel restores zeros
// after reading, so every kernel_launch sees a clean scratch (graph-replay
// safe, no zeroing kernel needed).
__device__ float2 g_bin[BINS];

// ---------------------------------------------------------------------------
// Pass 1: scatter-accumulate. Each thread handles 4 consecutive elements of
// one batch's channel-0 slice via float4/int4 loads. One red.global.add.v2.f32
// per element updates {sum, cnt} in a single L2 atomic transaction.
// vals layout [B, C, N] -> channel 0 of batch b starts at b*C*N.
// ---------------------------------------------------------------------------
__device__ __forceinline__ void red_v2(float2* p, float v) {
    asm volatile("red.global.add.v2.f32 [%0], {%1, %2};"
                 :: "l"(p), "f"(v), "f"(1.0f) : "memory");
}

__global__ void accum_kernel(const float* __restrict__ vals,
                             const int*   __restrict__ pix) {
    const int t = blockIdx.x * blockDim.x + threadIdx.x;  // 0 .. B*N/4-1
    const int per_batch = NN / 4;                 // 131072 vec4 per batch
    const int b = t / per_batch;
    const int v = t % per_batch;

    const float4 vv = reinterpret_cast<const float4*>(
        vals + (long long)b * C * NN)[v];
    const int4 pp = reinterpret_cast<const int4*>(
        pix + (long long)b * NN)[v];

    float2* __restrict__ bin = g_bin + b * NPIX;

    red_v2(bin + pp.x, vv.x);
    red_v2(bin + pp.y, vv.y);
    red_v2(bin + pp.z, vv.z);
    red_v2(bin + pp.w, vv.w);
}

// ---------------------------------------------------------------------------
// Pass 2: compute mean, broadcast across C=16 output channels, reset bin.
// COALESCED mapping: one thread per output float4 (4 threads per bin), so
// consecutive lanes write consecutive 16B chunks -> 4 wavefronts per STG.128
// instead of 32 with the thread-per-bin layout.
// Output layout [B, NPIX, C], C contiguous: bin i owns out[16i .. 16i+15].
// ---------------------------------------------------------------------------
__global__ void write_kernel(float* __restrict__ out) {
    int i = blockIdx.x * blockDim.x + threadIdx.x;   // 0 .. BINS*4-1
    int bin = i >> 2;
    float2 sc = g_bin[bin];                           // broadcast in 4-lane group
    if ((i & 3) == 0)
        g_bin[bin] = make_float2(0.f, 0.f);           // self-clean for replay
    float m = sc.x / fmaxf(sc.y, 1.0f);
    reinterpret_cast<float4*>(out)[i] = make_float4(m, m, m, m);
}

// ---------------------------------------------------------------------------
extern "C" void kernel_launch(void* const* d_in, const int* in_sizes, int n_in,
                              void* d_out, int out_size) {
    const float* vals = (const float*)d_in[0];   // [B, C, N] f32
    const int*   pix  = (const int*)d_in[1];     // [B, N] i32
    float*       out  = (float*)d_out;           // [B, NPIX, C] f32

    (void)in_sizes; (void)n_in; (void)out_size;

    {
        const int n = B * (NN / 4);              // 1,048,576 threads
        accum_kernel<<<n / 256, 256>>>(vals, pix);
    }
    {
        const int n = BINS * 4;                  // 1,572,864 threads
        write_kernel<<<n / 256, 256>>>(out);
    }
}